// round 3
// baseline (speedup 1.0000x reference)
#include <cuda_runtime.h>
#include <math.h>

#define NE  256
#define DD  256
#define NH  4
#define DHD 64
#define NL  2
#define P_TOTAL (NE*(NE-1)/2)        /* 32640 */
#define PPB 8
#define NBLOCKS (P_TOTAL/PPB)        /* 4080 */
#define SMEM_BYTES (4*PPB*2*256*4)   /* 65536: h,q,k,v */

// ---------------- scratch (device globals; no allocations) ----------------
__device__ float2 g_A[NE*NE];
__device__ double g_acc[2];          // bosonic log sum (re, im)
__device__ double g_lu_logabs, g_lu_arg;
__device__ int    g_lu_par;

__device__ __forceinline__ float f4c(const float4& v, int u) {
    return u==0 ? v.x : (u==1 ? v.y : (u==2 ? v.z : v.w));
}

// out[p][s][tid] accumulator: acc[p][s] = sum_e in[p][s][e] * W[e*256+tid]
__device__ __forceinline__ void gemm256(const float* __restrict__ W,
                                        const float* in, float acc[PPB][2], int tid)
{
    #pragma unroll
    for (int p = 0; p < PPB; p++) { acc[p][0] = 0.f; acc[p][1] = 0.f; }
    for (int e = 0; e < 256; e += 4) {
        float4 hv[PPB][2];
        #pragma unroll
        for (int p = 0; p < PPB; p++) {
            hv[p][0] = *(const float4*)(in + (p*2+0)*256 + e);
            hv[p][1] = *(const float4*)(in + (p*2+1)*256 + e);
        }
        #pragma unroll
        for (int u = 0; u < 4; u++) {
            float w = __ldg(W + (e+u)*256 + tid);
            #pragma unroll
            for (int p = 0; p < PPB; p++) {
                acc[p][0] = fmaf(f4c(hv[p][0], u), w, acc[p][0]);
                acc[p][1] = fmaf(f4c(hv[p][1], u), w, acc[p][1]);
            }
        }
    }
}

__device__ __forceinline__ void layernorm(float* shh,
                                          const float* __restrict__ sc,
                                          const float* __restrict__ bi,
                                          float red[PPB][2][2][8], int tid)
{
    int lane = tid & 31, wrp = tid >> 5;
    float x[PPB][2];
    #pragma unroll
    for (int p = 0; p < PPB; p++) {
        #pragma unroll
        for (int s = 0; s < 2; s++) {
            float v = shh[(p*2+s)*256 + tid];
            x[p][s] = v;
            float s1 = v, s2 = v*v;
            #pragma unroll
            for (int off = 16; off; off >>= 1) {
                s1 += __shfl_xor_sync(0xffffffffu, s1, off);
                s2 += __shfl_xor_sync(0xffffffffu, s2, off);
            }
            if (lane == 0) { red[p][s][0][wrp] = s1; red[p][s][1][wrp] = s2; }
        }
    }
    __syncthreads();
    float scv = __ldg(sc + tid), biv = __ldg(bi + tid);
    #pragma unroll
    for (int p = 0; p < PPB; p++) {
        #pragma unroll
        for (int s = 0; s < 2; s++) {
            float s1 = 0.f, s2 = 0.f;
            #pragma unroll
            for (int w = 0; w < 8; w++) { s1 += red[p][s][0][w]; s2 += red[p][s][1][w]; }
            float m   = s1 * (1.f/256.f);
            float var = s2 * (1.f/256.f) - m*m;
            shh[(p*2+s)*256 + tid] = (x[p][s] - m) * rsqrtf(var + 1e-5f) * scv + biv;
        }
    }
    __syncthreads();
}

// ---------------- pair transformer + orbitals -> antisymmetric A ----------
__global__ void __launch_bounds__(256, 2) pair_kernel(
    const float* __restrict__ electrons,
    const float* __restrict__ W_in,
    const float* __restrict__ Wq, const float* __restrict__ bq,
    const float* __restrict__ Wk, const float* __restrict__ bk,
    const float* __restrict__ Wv, const float* __restrict__ bv,
    const float* __restrict__ Wo, const float* __restrict__ bo,
    const float* __restrict__ W1, const float* __restrict__ ln1_s, const float* __restrict__ ln1_b,
    const float* __restrict__ W2, const float* __restrict__ b2,
    const float* __restrict__ ln2_s, const float* __restrict__ ln2_b,
    const float* __restrict__ Worb_r, const float* __restrict__ Worb_i)
{
    extern __shared__ float smem[];
    float* shh = smem;
    float* shq = shh + PPB*2*256;
    float* shk = shq + PPB*2*256;
    float* shv = shk + PPB*2*256;

    __shared__ float s_attn[PPB][NH][2][2];
    __shared__ float s_feat[PPB][2][3];
    __shared__ float s_tp[PPB][2][2];
    __shared__ int   s_ij[PPB][2];
    __shared__ float s_red[PPB][2][2][8];
    __shared__ float s_orb[PPB][8];

    int tid = threadIdx.x;

    if (tid < PPB) {
        long long p = (long long)blockIdx.x * PPB + tid;
        double pd = (double)p;
        int i = (int)floor((2.0*NE - 1.0 - sqrt((2.0*NE-1.0)*(2.0*NE-1.0) - 8.0*pd)) * 0.5);
        if (i < 0) i = 0;
        if (i > NE-2) i = NE-2;
        while (i > 0 && (long long)i*(2*NE-1-i)/2 > p) i--;
        while ((long long)(i+1)*(2*NE-1-(i+1))/2 <= p) i++;
        long long base = (long long)i*(2*NE-1-i)/2;
        int j = (int)(p - base) + i + 1;
        s_ij[tid][0] = i; s_ij[tid][1] = j;
    }
    __syncthreads();
    if (tid < PPB*2) {
        int p = tid >> 1, s = tid & 1;
        int e = s_ij[p][s];
        float th = electrons[2*e], ph = electrons[2*e+1];
        s_tp[p][s][0] = th; s_tp[p][s][1] = ph;
        float st, ct, sp, cp;
        sincosf(th, &st, &ct);
        sincosf(ph, &sp, &cp);
        s_feat[p][s][0] = ct;
        s_feat[p][s][1] = st*cp;
        s_feat[p][s][2] = st*sp;
    }
    __syncthreads();

    // h = feat @ W_in
    {
        float w0 = __ldg(W_in + tid), w1 = __ldg(W_in + 256 + tid), w2 = __ldg(W_in + 512 + tid);
        #pragma unroll
        for (int p = 0; p < PPB; p++)
            #pragma unroll
            for (int s = 0; s < 2; s++)
                shh[(p*2+s)*256 + tid] = s_feat[p][s][0]*w0 + s_feat[p][s][1]*w1 + s_feat[p][s][2]*w2;
    }
    __syncthreads();

    float acc[PPB][2];
    for (int l = 0; l < NL; l++) {
        const float* Wq_l = Wq + l*65536;  const float* bq_l = bq + l*256;
        const float* Wk_l = Wk + l*65536;  const float* bk_l = bk + l*256;
        const float* Wv_l = Wv + l*65536;  const float* bv_l = bv + l*256;
        const float* Wo_l = Wo + l*65536;  const float* bo_l = bo + l*256;
        const float* W1_l = W1 + l*65536;
        const float* W2_l = W2 + l*65536;  const float* b2_l = b2 + l*256;

        gemm256(Wq_l, shh, acc, tid);
        { float b = __ldg(bq_l + tid);
          #pragma unroll
          for (int p = 0; p < PPB; p++) { shq[(p*2+0)*256+tid] = acc[p][0]+b; shq[(p*2+1)*256+tid] = acc[p][1]+b; } }
        gemm256(Wk_l, shh, acc, tid);
        { float b = __ldg(bk_l + tid);
          #pragma unroll
          for (int p = 0; p < PPB; p++) { shk[(p*2+0)*256+tid] = acc[p][0]+b; shk[(p*2+1)*256+tid] = acc[p][1]+b; } }
        gemm256(Wv_l, shh, acc, tid);
        { float b = __ldg(bv_l + tid);
          #pragma unroll
          for (int p = 0; p < PPB; p++) { shv[(p*2+0)*256+tid] = acc[p][0]+b; shv[(p*2+1)*256+tid] = acc[p][1]+b; } }
        __syncthreads();

        // attention (seq len 2, 4 heads)
        if (tid < PPB*8) {
            int p = tid >> 3, r = tid & 7, hh = r >> 1, s = r & 1;
            const float* qv = shq + (p*2+s)*256 + hh*DHD;
            const float* k0 = shk + (p*2+0)*256 + hh*DHD;
            const float* k1 = shk + (p*2+1)*256 + hh*DHD;
            float l0 = 0.f, l1 = 0.f;
            #pragma unroll 8
            for (int d = 0; d < DHD; d++) { float q = qv[d]; l0 = fmaf(q, k0[d], l0); l1 = fmaf(q, k1[d], l1); }
            l0 *= 0.125f; l1 *= 0.125f;
            float mx = fmaxf(l0, l1);
            float e0 = expf(l0 - mx), e1 = expf(l1 - mx);
            float inv = 1.f / (e0 + e1);
            s_attn[p][hh][s][0] = e0 * inv;
            s_attn[p][hh][s][1] = e1 * inv;
        }
        __syncthreads();

        // o = attn @ v  (overwrite shq)
        {
            int hh = tid >> 6;
            #pragma unroll
            for (int p = 0; p < PPB; p++) {
                float v0 = shv[(p*2+0)*256+tid], v1 = shv[(p*2+1)*256+tid];
                shq[(p*2+0)*256+tid] = s_attn[p][hh][0][0]*v0 + s_attn[p][hh][0][1]*v1;
                shq[(p*2+1)*256+tid] = s_attn[p][hh][1][0]*v0 + s_attn[p][hh][1][1]*v1;
            }
        }
        __syncthreads();

        // mha = o @ Wo + bo -> shk
        gemm256(Wo_l, shq, acc, tid);
        { float b = __ldg(bo_l + tid);
          #pragma unroll
          for (int p = 0; p < PPB; p++) { shk[(p*2+0)*256+tid] = acc[p][0]+b; shk[(p*2+1)*256+tid] = acc[p][1]+b; } }
        __syncthreads();

        // h += mha @ W1
        gemm256(W1_l, shk, acc, tid);
        #pragma unroll
        for (int p = 0; p < PPB; p++) { shh[(p*2+0)*256+tid] += acc[p][0]; shh[(p*2+1)*256+tid] += acc[p][1]; }
        __syncthreads();
        layernorm(shh, ln1_s + l*256, ln1_b + l*256, s_red, tid);

        // h += tanh(h @ W2 + b2)
        gemm256(W2_l, shh, acc, tid);
        __syncthreads();
        { float b = __ldg(b2_l + tid);
          #pragma unroll
          for (int p = 0; p < PPB; p++) {
              shh[(p*2+0)*256+tid] += tanhf(acc[p][0] + b);
              shh[(p*2+1)*256+tid] += tanhf(acc[p][1] + b);
          } }
        __syncthreads();
        layernorm(shh, ln2_s + l*256, ln2_b + l*256, s_red, tid);
    }

    // orbital projections: 8 warps = (ri, s, c) combos
    {
        int wrp = tid >> 5, lane = tid & 31;
        const float* Ws = (wrp >= 4) ? Worb_i : Worb_r;
        int s = (wrp >> 1) & 1, c = wrp & 1;
        for (int p = 0; p < PPB; p++) {
            float sum = 0.f;
            for (int d = lane; d < 256; d += 32)
                sum = fmaf(shh[(p*2+s)*256 + d], __ldg(Ws + d*2 + c), sum);
            #pragma unroll
            for (int off = 16; off; off >>= 1) sum += __shfl_xor_sync(0xffffffffu, sum, off);
            if (lane == 0) s_orb[p][wrp] = sum;
        }
    }
    __syncthreads();

    if (tid < PPB) {
        int p = tid;
        float th0 = s_tp[p][0][0], ph0 = s_tp[p][0][1];
        float th1 = s_tp[p][1][0], ph1 = s_tp[p][1][1];
        float c0, s0, c1, s1;
        sincosf(0.5f*th0, &s0, &c0);
        sincosf(0.5f*th1, &s1, &c1);
        float hd = 0.5f*(ph0 - ph1);
        float chd, shd; sincosf(hd, &shd, &chd);
        float re = (c0*s1 - c1*s0) * chd;
        float im = (c0*s1 + c1*s0) * shd;
        float chord2 = re*re + im*im;
        float trunc = 1.f - expf(-100.f * chord2);
        float t2 = trunc * trunc;
        float a_r = s_orb[p][0], b_r = s_orb[p][1], c_r = s_orb[p][2], d_r = s_orb[p][3];
        float a_i = s_orb[p][4], b_i = s_orb[p][5], c_i = s_orb[p][6], d_i = s_orb[p][7];
        // det of [[o00,o01],[o10,o11]], o_sc = (real idx s*2+c, imag idx 4+s*2+c)
        float det_r = (a_r*d_r - a_i*d_i) - (b_r*c_r - b_i*c_i);
        float det_i = (a_r*d_i + a_i*d_r) - (b_r*c_i + b_i*c_r);
        det_r *= t2; det_i *= t2;
        int i = s_ij[p][0], j = s_ij[p][1];
        g_A[i*NE + j] = make_float2(det_r, det_i);
        g_A[j*NE + i] = make_float2(-det_r, -det_i);
    }
}

// ---------------- cusp matrix + bosonic log sum ---------------------------
__global__ void cusp_bos_kernel(const float* __restrict__ electrons)
{
    int i = blockIdx.x, j = threadIdx.x;
    __shared__ double s_red[2][8];
    float thi = electrons[2*i], phi_ = electrons[2*i+1];
    float thj = electrons[2*j], phj  = electrons[2*j+1];
    float ci, si, cj, sj;
    sincosf(0.5f*thi, &si, &ci);
    sincosf(0.5f*thj, &sj, &cj);
    float hd = 0.5f*(phi_ - phj);
    float chd, shd; sincosf(hd, &shd, &chd);
    float er = (ci*sj - si*cj) * chd;
    float ei = (ci*sj + si*cj) * shd;

    float eye = (i == j) ? 1.f : 0.f;
    float cr = er + eye, cim = ei;
    float rc2 = cr*cr + cim*cim;
    float g = expf(-100.f * rc2);
    float2 a = (i == j) ? make_float2(0.f, 0.f) : g_A[i*NE + j];
    a.x += cr * g;
    a.y += cim * g;
    g_A[i*NE + j] = a;

    double lr = 0.0, li = 0.0;
    if (i != j) {
        float rho2 = er*er + ei*ei;
        lr = 0.5 * log((double)(0.01f + rho2));   // log|masked|
        li = (double)atan2f(ei, er);              // arg(masked) = arg(elem)
    }
    int lane = j & 31, wrp = j >> 5;
    #pragma unroll
    for (int off = 16; off; off >>= 1) {
        lr += __shfl_xor_sync(0xffffffffu, lr, off);
        li += __shfl_xor_sync(0xffffffffu, li, off);
    }
    if (lane == 0) { s_red[0][wrp] = lr; s_red[1][wrp] = li; }
    __syncthreads();
    if (j == 0) {
        double a0 = 0.0, a1 = 0.0;
        #pragma unroll
        for (int w = 0; w < 8; w++) { a0 += s_red[0][w]; a1 += s_red[1][w]; }
        atomicAdd(&g_acc[0], a0);
        atomicAdd(&g_acc[1], a1);
    }
}

// ---------------- complex LU with partial pivoting (slogdet) --------------
__device__ __forceinline__ float2 cmul(float2 a, float2 b) {
    return make_float2(a.x*b.x - a.y*b.y, a.x*b.y + a.y*b.x);
}

__global__ void __launch_bounds__(1024) lu_kernel()
{
    __shared__ float2 s_prow[256];
    __shared__ float2 s_l[256];
    __shared__ float  s_mx[8];
    __shared__ int    s_mi[8];
    __shared__ float2 s_inv;
    __shared__ int    s_piv;
    int tid = threadIdx.x;
    double logabs = 0.0, argsum = 0.0;
    int par = 0;

    for (int k = 0; k < 256; k++) {
        if (tid < 256) {
            float v = -1.f; int idx = tid;
            if (tid >= k) { float2 a = g_A[tid*256 + k]; v = fabsf(a.x) + fabsf(a.y); }
            #pragma unroll
            for (int off = 16; off; off >>= 1) {
                float ov = __shfl_xor_sync(0xffffffffu, v, off);
                int   oi = __shfl_xor_sync(0xffffffffu, idx, off);
                if (ov > v) { v = ov; idx = oi; }
            }
            if ((tid & 31) == 0) { s_mx[tid>>5] = v; s_mi[tid>>5] = idx; }
        }
        __syncthreads();
        if (tid == 0) {
            float bv = -1.f; int bi = k;
            #pragma unroll
            for (int w = 0; w < 8; w++) if (s_mx[w] > bv) { bv = s_mx[w]; bi = s_mi[w]; }
            s_piv = bi;
        }
        __syncthreads();
        int pv = s_piv;
        if (pv != k && tid < 256) {
            float2 t = g_A[k*256 + tid];
            g_A[k*256 + tid] = g_A[pv*256 + tid];
            g_A[pv*256 + tid] = t;
        }
        __syncthreads();
        if (tid == 0) {
            if (pv != k) par ^= 1;
            float2 u = g_A[k*256 + k];
            double n2 = (double)u.x*u.x + (double)u.y*u.y;
            logabs += 0.5 * log(n2);
            argsum += atan2((double)u.y, (double)u.x);
            float d = u.x*u.x + u.y*u.y;
            s_inv = make_float2(u.x/d, -u.y/d);
        }
        __syncthreads();
        if (tid < 256) {
            s_prow[tid] = g_A[k*256 + tid];
            if (tid > k) {
                float2 l = cmul(g_A[tid*256 + k], s_inv);
                s_l[tid] = l;
                g_A[tid*256 + k] = l;
            }
        }
        __syncthreads();
        {
            int c = tid & 255, r0 = tid >> 8;
            if (c > k) {
                float2 pr = s_prow[c];
                #pragma unroll 4
                for (int i = k + 1 + r0; i < 256; i += 4) {
                    float2 l = s_l[i];
                    float2 a = g_A[i*256 + c];
                    a.x -= l.x*pr.x - l.y*pr.y;
                    a.y -= l.x*pr.y + l.y*pr.x;
                    g_A[i*256 + c] = a;
                }
            }
        }
        __syncthreads();
    }
    if (tid == 0) { g_lu_logabs = logabs; g_lu_arg = argsum; g_lu_par = par; }
}

// ---------------- init + finalize -----------------------------------------
__global__ void init_kernel() { g_acc[0] = 0.0; g_acc[1] = 0.0; }

__global__ void finalize_kernel(float* out)
{
    const double PI = 3.14159265358979323846;
    double logabs = g_lu_logabs;
    double arg = g_lu_arg + (g_lu_par ? PI : 0.0);
    double w = fmod(arg, 2.0*PI);
    if (w >  PI) w -= 2.0*PI;
    if (w <= -PI) w += 2.0*PI;
    out[0] = (float)(0.5*logabs + g_acc[0]);
    out[1] = (float)(0.5*w      + g_acc[1]);
}

// ---------------- launch ---------------------------------------------------
extern "C" void kernel_launch(void* const* d_in, const int* in_sizes, int n_in,
                              void* d_out, int out_size)
{
    const float* electrons = (const float*)d_in[0];
    const float* W_in   = (const float*)d_in[1];
    const float* Wq     = (const float*)d_in[2];
    const float* bq     = (const float*)d_in[3];
    const float* Wk     = (const float*)d_in[4];
    const float* bk     = (const float*)d_in[5];
    const float* Wv     = (const float*)d_in[6];
    const float* bv     = (const float*)d_in[7];
    const float* Wo     = (const float*)d_in[8];
    const float* bo     = (const float*)d_in[9];
    const float* W1     = (const float*)d_in[10];
    const float* ln1_s  = (const float*)d_in[11];
    const float* ln1_b  = (const float*)d_in[12];
    const float* W2     = (const float*)d_in[13];
    const float* b2     = (const float*)d_in[14];
    const float* ln2_s  = (const float*)d_in[15];
    const float* ln2_b  = (const float*)d_in[16];
    const float* Worb_r = (const float*)d_in[17];
    const float* Worb_i = (const float*)d_in[18];

    cudaFuncSetAttribute(pair_kernel, cudaFuncAttributeMaxDynamicSharedMemorySize, SMEM_BYTES);

    init_kernel<<<1, 1>>>();
    pair_kernel<<<NBLOCKS, 256, SMEM_BYTES>>>(electrons, W_in, Wq, bq, Wk, bk, Wv, bv,
                                              Wo, bo, W1, ln1_s, ln1_b, W2, b2,
                                              ln2_s, ln2_b, Worb_r, Worb_i);
    cusp_bos_kernel<<<NE, NE>>>(electrons);
    lu_kernel<<<1, 1024>>>();
    finalize_kernel<<<1, 1>>>((float*)d_out);
}

// round 6
// speedup vs baseline: 1.6455x; 1.6455x over previous
#include <cuda_runtime.h>
#include <cuda_bf16.h>
#include <math.h>
#include <cstdint>

#define NE  256
#define NL  2
#define P_TOTAL 32640
#define PPB 16
#define MTOK 32                        /* 2*PPB tokens per CTA */
#define NBLOCKS (P_TOTAL/PPB)          /* 2040 */
#define RS  264                        /* padded row stride, bf16 elems */
#define RSB (RS*2)                     /* 528 bytes */
#define PL  (MTOK*RS)                  /* one activation plane, halves (8448) */
#define PLB (PL*2)                     /* plane bytes (16896) */
#define WCH (64*RS)                    /* one W chunk buf: 32 hi rows + 32 lo rows */
#define WCHB (WCH*2)                   /* 33792 bytes */
#define SMEM_BYTES (8*PL*2 + 2*WCHB)   /* 135168 + 67584 = 202752 */

// ---------------- device globals (no allocations) --------------------------
__device__ __nv_bfloat16 g_Wb_hi[12*65536];  // [l][{Wq,Wk,Wv,Wo,W1,W2}][256*256]
__device__ __nv_bfloat16 g_Wb_lo[12*65536];
__device__ float2 g_A[NE*NE];
__device__ double g_acc[2];
__device__ double g_lu_logabs, g_lu_arg;
__device__ int    g_lu_par;

// ---------------- weight conversion fp32 -> split bf16 ---------------------
__global__ void convert_weights(const float* __restrict__ Wq, const float* __restrict__ Wk,
                                const float* __restrict__ Wv, const float* __restrict__ Wo,
                                const float* __restrict__ W1, const float* __restrict__ W2)
{
    int idx = blockIdx.x * 256 + threadIdx.x;       // 0 .. 12*65536-1
    int m   = idx >> 16;
    int off = idx & 65535;
    int l = m / 6, w = m % 6;
    const float* src;
    switch (w) {
        case 0: src = Wq; break;  case 1: src = Wk; break;  case 2: src = Wv; break;
        case 3: src = Wo; break;  case 4: src = W1; break;  default: src = W2; break;
    }
    float v = src[l*65536 + off];
    __nv_bfloat16 hi = __float2bfloat16_rn(v);
    g_Wb_hi[idx] = hi;
    g_Wb_lo[idx] = __float2bfloat16_rn(v - __bfloat162float(hi));
}

// ---------------- helpers ---------------------------------------------------
__device__ __forceinline__ uint32_t smem_u32(const void* p) {
    return (uint32_t)__cvta_generic_to_shared(p);
}

__device__ __forceinline__ void sst(__nv_bfloat16* h, __nv_bfloat16* l, float x) {
    __nv_bfloat16 hi = __float2bfloat16_rn(x);
    *h = hi;
    *l = __float2bfloat16_rn(x - __bfloat162float(hi));
}

__device__ __forceinline__ float rec(const __nv_bfloat16* h, const __nv_bfloat16* l, int idx) {
    return __bfloat162float(h[idx]) + __bfloat162float(l[idx]);
}

// load one 32-k-row chunk of W (hi rows 0..31, lo rows 32..63 of the chunk buf)
__device__ __forceinline__ void cp_load_chunk(const __nv_bfloat16* __restrict__ gWhi,
                                              const __nv_bfloat16* __restrict__ gWlo,
                                              int chunk, uint32_t sWbuf, int tid)
{
    #pragma unroll
    for (int i = 0; i < 8; i++) {
        int g = tid + i*256;                  // 2048 granules of 16B
        int plane = g >> 10;                  // 0=hi, 1=lo
        int row = (g >> 5) & 31, c16 = g & 31;
        uint32_t s = sWbuf + (plane*32 + row)*RSB + c16*16;
        const __nv_bfloat16* base = plane ? gWlo : gWhi;
        const void* gp = base + (chunk*32 + row)*256 + c16*8;
        asm volatile("cp.async.cg.shared.global [%0],[%1],16;\n" :: "r"(s), "l"(gp));
    }
    asm volatile("cp.async.commit_group;\n");
}

// Split-bf16 GEMM: C[2][4][4] = warp-owned 32x32 fp32 tile of X(32x256) @ W(256x256)
// A: hi plane at sA, lo plane at sA+PLB. W streamed hi+lo, double buffered at sW.
__device__ __forceinline__ void mma_gemm(const __nv_bfloat16* __restrict__ gWhi,
                                         const __nv_bfloat16* __restrict__ gWlo,
                                         uint32_t sA, uint32_t sW,
                                         float C[2][4][4], int tid)
{
    int lane = tid & 31, warp = tid >> 5;
    #pragma unroll
    for (int a = 0; a < 2; a++)
        #pragma unroll
        for (int b = 0; b < 4; b++)
            #pragma unroll
            for (int d = 0; d < 4; d++) C[a][b][d] = 0.f;

    cp_load_chunk(gWhi, gWlo, 0, sW, tid);
    #pragma unroll 1
    for (int c = 0; c < 8; c++) {
        if (c < 7) {
            cp_load_chunk(gWhi, gWlo, c+1, sW + ((c+1)&1)*WCHB, tid);
            asm volatile("cp.async.wait_group 1;\n");
        } else {
            asm volatile("cp.async.wait_group 0;\n");
        }
        __syncthreads();
        uint32_t wb = sW + (c&1)*WCHB;
        #pragma unroll
        for (int ks = 0; ks < 2; ks++) {
            int k0 = c*32 + ks*16;
            uint32_t ahi[2][4], alo[2][4], bhi[2][4], blo[2][4];
            #pragma unroll
            for (int mi = 0; mi < 2; mi++) {
                uint32_t addr = sA + (mi*16 + (lane & 15))*RSB + (k0 + ((lane >> 4) << 3))*2;
                asm volatile("ldmatrix.sync.aligned.m8n8.x4.shared.b16 {%0,%1,%2,%3},[%4];\n"
                    : "=r"(ahi[mi][0]), "=r"(ahi[mi][1]), "=r"(ahi[mi][2]), "=r"(ahi[mi][3]) : "r"(addr));
                asm volatile("ldmatrix.sync.aligned.m8n8.x4.shared.b16 {%0,%1,%2,%3},[%4];\n"
                    : "=r"(alo[mi][0]), "=r"(alo[mi][1]), "=r"(alo[mi][2]), "=r"(alo[mi][3]) : "r"(addr + PLB));
            }
            #pragma unroll
            for (int nh = 0; nh < 2; nh++) {
                uint32_t addr = wb + (ks*16 + (lane & 15))*RSB
                              + (warp*32 + nh*16 + ((lane >> 4) << 3))*2;
                asm volatile("ldmatrix.sync.aligned.m8n8.x4.trans.shared.b16 {%0,%1,%2,%3},[%4];\n"
                    : "=r"(bhi[nh][0]), "=r"(bhi[nh][1]), "=r"(bhi[nh][2]), "=r"(bhi[nh][3]) : "r"(addr));
                asm volatile("ldmatrix.sync.aligned.m8n8.x4.trans.shared.b16 {%0,%1,%2,%3},[%4];\n"
                    : "=r"(blo[nh][0]), "=r"(blo[nh][1]), "=r"(blo[nh][2]), "=r"(blo[nh][3]) : "r"(addr + 32*RSB));
            }
            #pragma unroll
            for (int mi = 0; mi < 2; mi++)
                #pragma unroll
                for (int ni = 0; ni < 4; ni++) {
                    uint32_t bh0 = bhi[ni>>1][(ni&1)*2], bh1 = bhi[ni>>1][(ni&1)*2 + 1];
                    uint32_t bl0 = blo[ni>>1][(ni&1)*2], bl1 = blo[ni>>1][(ni&1)*2 + 1];
                    asm volatile("mma.sync.aligned.m16n8k16.row.col.f32.bf16.bf16.f32 "
                        "{%0,%1,%2,%3},{%4,%5,%6,%7},{%8,%9},{%0,%1,%2,%3};\n"
                        : "+f"(C[mi][ni][0]), "+f"(C[mi][ni][1]),
                          "+f"(C[mi][ni][2]), "+f"(C[mi][ni][3])
                        : "r"(ahi[mi][0]), "r"(ahi[mi][1]), "r"(ahi[mi][2]), "r"(ahi[mi][3]),
                          "r"(bh0), "r"(bh1));
                    asm volatile("mma.sync.aligned.m16n8k16.row.col.f32.bf16.bf16.f32 "
                        "{%0,%1,%2,%3},{%4,%5,%6,%7},{%8,%9},{%0,%1,%2,%3};\n"
                        : "+f"(C[mi][ni][0]), "+f"(C[mi][ni][1]),
                          "+f"(C[mi][ni][2]), "+f"(C[mi][ni][3])
                        : "r"(alo[mi][0]), "r"(alo[mi][1]), "r"(alo[mi][2]), "r"(alo[mi][3]),
                          "r"(bh0), "r"(bh1));
                    asm volatile("mma.sync.aligned.m16n8k16.row.col.f32.bf16.bf16.f32 "
                        "{%0,%1,%2,%3},{%4,%5,%6,%7},{%8,%9},{%0,%1,%2,%3};\n"
                        : "+f"(C[mi][ni][0]), "+f"(C[mi][ni][1]),
                          "+f"(C[mi][ni][2]), "+f"(C[mi][ni][3])
                        : "r"(ahi[mi][0]), "r"(ahi[mi][1]), "r"(ahi[mi][2]), "r"(ahi[mi][3]),
                          "r"(bl0), "r"(bl1));
                }
        }
        __syncthreads();
    }
}

// layernorm in place over split planes; each warp owns 4 rows (row fits in warp)
__device__ __forceinline__ void lnorm(__nv_bfloat16* Hh, __nv_bfloat16* Hl,
                                      const float* __restrict__ sc,
                                      const float* __restrict__ bi, int tid)
{
    int lane = tid & 31, warp = tid >> 5;
    #pragma unroll 1
    for (int rr = 0; rr < 4; rr++) {
        int row = warp*4 + rr;
        float xs[8];
        float s1 = 0.f, s2 = 0.f;
        #pragma unroll
        for (int i = 0; i < 8; i++) {
            int col = lane*8 + i;
            float f = rec(Hh, Hl, row*RS + col);
            xs[i] = f;
            s1 += f; s2 += f*f;
        }
        #pragma unroll
        for (int off = 16; off; off >>= 1) {
            s1 += __shfl_xor_sync(0xffffffffu, s1, off);
            s2 += __shfl_xor_sync(0xffffffffu, s2, off);
        }
        float m   = s1 * (1.f/256.f);
        float var = s2 * (1.f/256.f) - m*m;
        float inv = rsqrtf(var + 1e-5f);
        #pragma unroll
        for (int i = 0; i < 8; i++) {
            int col = lane*8 + i;
            float y = (xs[i] - m)*inv*__ldg(sc+col) + __ldg(bi+col);
            sst(Hh + row*RS + col, Hl + row*RS + col, y);
        }
    }
}

// ---------------- pair transformer (split-bf16 tensor-core) ----------------
__global__ void __launch_bounds__(256, 1) pair_kernel(
    const float* __restrict__ electrons,
    const float* __restrict__ W_in,
    const float* __restrict__ bq, const float* __restrict__ bk,
    const float* __restrict__ bv, const float* __restrict__ bo,
    const float* __restrict__ ln1_s, const float* __restrict__ ln1_b,
    const float* __restrict__ b2,
    const float* __restrict__ ln2_s, const float* __restrict__ ln2_b,
    const float* __restrict__ Worb_r, const float* __restrict__ Worb_i)
{
    extern __shared__ __nv_bfloat16 smem[];
    __nv_bfloat16* Hh = smem;            // planes: [32][RS] each
    __nv_bfloat16* Hl = Hh + PL;
    __nv_bfloat16* Qh = Hl + PL;
    __nv_bfloat16* Ql = Qh + PL;
    __nv_bfloat16* Kh = Ql + PL;
    __nv_bfloat16* Kl = Kh + PL;
    __nv_bfloat16* Vh = Kl + PL;
    __nv_bfloat16* Vl = Vh + PL;
    uint32_t sHb = smem_u32(Hh), sQb = smem_u32(Qh), sKb = smem_u32(Kh);
    uint32_t sWb = smem_u32(Vl + PL);    // W chunks after 8 planes

    __shared__ float s_feat[PPB][2][3];
    __shared__ float s_tp[PPB][2][2];
    __shared__ int   s_ij[PPB][2];
    __shared__ float s_attn[PPB][4][2][2];
    __shared__ float s_orb[PPB][8];

    int tid = threadIdx.x;
    int lane = tid & 31, warp = tid >> 5;

    // ---- pair index decode ----
    if (tid < PPB) {
        long long p = (long long)blockIdx.x * PPB + tid;
        double pd = (double)p;
        int i = (int)floor((2.0*NE - 1.0 - sqrt((2.0*NE-1.0)*(2.0*NE-1.0) - 8.0*pd)) * 0.5);
        if (i < 0) i = 0;
        if (i > NE-2) i = NE-2;
        while (i > 0 && (long long)i*(2*NE-1-i)/2 > p) i--;
        while ((long long)(i+1)*(2*NE-1-(i+1))/2 <= p) i++;
        long long base = (long long)i*(2*NE-1-i)/2;
        int j = (int)(p - base) + i + 1;
        s_ij[tid][0] = i; s_ij[tid][1] = j;
    }
    __syncthreads();
    if (tid < PPB*2) {
        int p = tid >> 1, s = tid & 1;
        int e = s_ij[p][s];
        float th = electrons[2*e], ph = electrons[2*e+1];
        s_tp[p][s][0] = th; s_tp[p][s][1] = ph;
        float st, ct, sp, cp;
        sincosf(th, &st, &ct);
        sincosf(ph, &sp, &cp);
        s_feat[p][s][0] = ct;
        s_feat[p][s][1] = st*cp;
        s_feat[p][s][2] = st*sp;
    }
    __syncthreads();

    // ---- h0 = feat @ W_in ----
    {
        float w0 = __ldg(W_in + tid), w1 = __ldg(W_in + 256 + tid), w2 = __ldg(W_in + 512 + tid);
        #pragma unroll 1
        for (int t = 0; t < MTOK; t++) {
            int p = t >> 1, s = t & 1;
            float hv = s_feat[p][s][0]*w0 + s_feat[p][s][1]*w1 + s_feat[p][s][2]*w2;
            sst(Hh + t*RS + tid, Hl + t*RS + tid, hv);
        }
    }
    __syncthreads();

    float C[2][4][4];
    for (int l = 0; l < NL; l++) {
        const __nv_bfloat16* gWq_h = g_Wb_hi + (l*6+0)*65536; const __nv_bfloat16* gWq_l = g_Wb_lo + (l*6+0)*65536;
        const __nv_bfloat16* gWk_h = g_Wb_hi + (l*6+1)*65536; const __nv_bfloat16* gWk_l = g_Wb_lo + (l*6+1)*65536;
        const __nv_bfloat16* gWv_h = g_Wb_hi + (l*6+2)*65536; const __nv_bfloat16* gWv_l = g_Wb_lo + (l*6+2)*65536;
        const __nv_bfloat16* gWo_h = g_Wb_hi + (l*6+3)*65536; const __nv_bfloat16* gWo_l = g_Wb_lo + (l*6+3)*65536;
        const __nv_bfloat16* gW1_h = g_Wb_hi + (l*6+4)*65536; const __nv_bfloat16* gW1_l = g_Wb_lo + (l*6+4)*65536;
        const __nv_bfloat16* gW2_h = g_Wb_hi + (l*6+5)*65536; const __nv_bfloat16* gW2_l = g_Wb_lo + (l*6+5)*65536;
        const float* bq_l = bq + l*256;
        const float* bk_l = bk + l*256;
        const float* bv_l = bv + l*256;
        const float* bo_l = bo + l*256;
        const float* b2_l = b2 + l*256;

        // ---- Q = h @ Wq + bq ----
        mma_gemm(gWq_h, gWq_l, sHb, sWb, C, tid);
        #pragma unroll
        for (int ni = 0; ni < 4; ni++) {
            int col = warp*32 + ni*8 + (lane & 3)*2;
            float v0 = __ldg(bq_l + col), v1 = __ldg(bq_l + col + 1);
            #pragma unroll
            for (int mi = 0; mi < 2; mi++)
                #pragma unroll
                for (int hf = 0; hf < 2; hf++) {
                    int row = mi*16 + (lane >> 2) + hf*8;
                    sst(Qh + row*RS + col,     Ql + row*RS + col,     C[mi][ni][hf*2]   + v0);
                    sst(Qh + row*RS + col + 1, Ql + row*RS + col + 1, C[mi][ni][hf*2+1] + v1);
                }
        }
        // ---- K = h @ Wk + bk ----
        mma_gemm(gWk_h, gWk_l, sHb, sWb, C, tid);
        #pragma unroll
        for (int ni = 0; ni < 4; ni++) {
            int col = warp*32 + ni*8 + (lane & 3)*2;
            float v0 = __ldg(bk_l + col), v1 = __ldg(bk_l + col + 1);
            #pragma unroll
            for (int mi = 0; mi < 2; mi++)
                #pragma unroll
                for (int hf = 0; hf < 2; hf++) {
                    int row = mi*16 + (lane >> 2) + hf*8;
                    sst(Kh + row*RS + col,     Kl + row*RS + col,     C[mi][ni][hf*2]   + v0);
                    sst(Kh + row*RS + col + 1, Kl + row*RS + col + 1, C[mi][ni][hf*2+1] + v1);
                }
        }
        // ---- V = h @ Wv + bv ----
        mma_gemm(gWv_h, gWv_l, sHb, sWb, C, tid);
        #pragma unroll
        for (int ni = 0; ni < 4; ni++) {
            int col = warp*32 + ni*8 + (lane & 3)*2;
            float v0 = __ldg(bv_l + col), v1 = __ldg(bv_l + col + 1);
            #pragma unroll
            for (int mi = 0; mi < 2; mi++)
                #pragma unroll
                for (int hf = 0; hf < 2; hf++) {
                    int row = mi*16 + (lane >> 2) + hf*8;
                    sst(Vh + row*RS + col,     Vl + row*RS + col,     C[mi][ni][hf*2]   + v0);
                    sst(Vh + row*RS + col + 1, Vl + row*RS + col + 1, C[mi][ni][hf*2+1] + v1);
                }
        }
        __syncthreads();

        // ---- attention logits + softmax (seq 2, 4 heads): 128 threads ----
        if (tid < PPB*8) {
            int p = tid >> 3, r = tid & 7, hh = r >> 1, s = r & 1;
            int qb = (p*2+s)*RS + hh*64;
            int k0b = (p*2+0)*RS + hh*64;
            int k1b = (p*2+1)*RS + hh*64;
            float l0 = 0.f, l1 = 0.f;
            #pragma unroll 8
            for (int d = 0; d < 64; d++) {
                float q = rec(Qh, Ql, qb + d);
                l0 = fmaf(q, rec(Kh, Kl, k0b + d), l0);
                l1 = fmaf(q, rec(Kh, Kl, k1b + d), l1);
            }
            l0 *= 0.125f; l1 *= 0.125f;
            float mx = fmaxf(l0, l1);
            float e0 = expf(l0 - mx), e1 = expf(l1 - mx);
            float inv = 1.f / (e0 + e1);
            s_attn[p][hh][s][0] = e0 * inv;
            s_attn[p][hh][s][1] = e1 * inv;
        }
        __syncthreads();

        // ---- o = attn @ v  -> overwrite Q planes ----
        {
            int c = tid;            // one column per thread
            int hh = c >> 6;
            #pragma unroll 1
            for (int t = 0; t < MTOK; t++) {
                int p = t >> 1, s = t & 1;
                float a0 = s_attn[p][hh][s][0], a1 = s_attn[p][hh][s][1];
                float v0 = rec(Vh, Vl, (p*2+0)*RS + c);
                float v1 = rec(Vh, Vl, (p*2+1)*RS + c);
                sst(Qh + t*RS + c, Ql + t*RS + c, a0*v0 + a1*v1);
            }
        }
        __syncthreads();

        // ---- mha = o @ Wo + bo  -> K planes ----
        mma_gemm(gWo_h, gWo_l, sQb, sWb, C, tid);
        #pragma unroll
        for (int ni = 0; ni < 4; ni++) {
            int col = warp*32 + ni*8 + (lane & 3)*2;
            float v0 = __ldg(bo_l + col), v1 = __ldg(bo_l + col + 1);
            #pragma unroll
            for (int mi = 0; mi < 2; mi++)
                #pragma unroll
                for (int hf = 0; hf < 2; hf++) {
                    int row = mi*16 + (lane >> 2) + hf*8;
                    sst(Kh + row*RS + col,     Kl + row*RS + col,     C[mi][ni][hf*2]   + v0);
                    sst(Kh + row*RS + col + 1, Kl + row*RS + col + 1, C[mi][ni][hf*2+1] + v1);
                }
        }
        // ---- h += mha @ W1 ----
        mma_gemm(gW1_h, gW1_l, sKb, sWb, C, tid);
        #pragma unroll
        for (int ni = 0; ni < 4; ni++) {
            int col = warp*32 + ni*8 + (lane & 3)*2;
            #pragma unroll
            for (int mi = 0; mi < 2; mi++)
                #pragma unroll
                for (int hf = 0; hf < 2; hf++) {
                    int row = mi*16 + (lane >> 2) + hf*8;
                    float h0v = rec(Hh, Hl, row*RS + col)     + C[mi][ni][hf*2];
                    float h1v = rec(Hh, Hl, row*RS + col + 1) + C[mi][ni][hf*2+1];
                    sst(Hh + row*RS + col,     Hl + row*RS + col,     h0v);
                    sst(Hh + row*RS + col + 1, Hl + row*RS + col + 1, h1v);
                }
        }
        __syncthreads();
        lnorm(Hh, Hl, ln1_s + l*256, ln1_b + l*256, tid);
        __syncthreads();

        // ---- h += tanh(h @ W2 + b2) ----
        mma_gemm(gW2_h, gW2_l, sHb, sWb, C, tid);
        #pragma unroll
        for (int ni = 0; ni < 4; ni++) {
            int col = warp*32 + ni*8 + (lane & 3)*2;
            float v0 = __ldg(b2_l + col), v1 = __ldg(b2_l + col + 1);
            #pragma unroll
            for (int mi = 0; mi < 2; mi++)
                #pragma unroll
                for (int hf = 0; hf < 2; hf++) {
                    int row = mi*16 + (lane >> 2) + hf*8;
                    float h0v = rec(Hh, Hl, row*RS + col)     + tanhf(C[mi][ni][hf*2]   + v0);
                    float h1v = rec(Hh, Hl, row*RS + col + 1) + tanhf(C[mi][ni][hf*2+1] + v1);
                    sst(Hh + row*RS + col,     Hl + row*RS + col,     h0v);
                    sst(Hh + row*RS + col + 1, Hl + row*RS + col + 1, h1v);
                }
        }
        __syncthreads();
        lnorm(Hh, Hl, ln2_s + l*256, ln2_b + l*256, tid);
        __syncthreads();
    }

    // ---- orbital projections: 8 warps = (ri, s, c) combos ----
    {
        const float* Ws = (warp >= 4) ? Worb_i : Worb_r;
        int s = (warp >> 1) & 1, c = warp & 1;
        #pragma unroll 1
        for (int p = 0; p < PPB; p++) {
            float sum = 0.f;
            int hb = (p*2+s)*RS;
            #pragma unroll
            for (int k = 0; k < 8; k++) {
                int d = lane + 32*k;
                sum = fmaf(rec(Hh, Hl, hb + d), __ldg(Ws + d*2 + c), sum);
            }
            #pragma unroll
            for (int off = 16; off; off >>= 1) sum += __shfl_xor_sync(0xffffffffu, sum, off);
            if (lane == 0) s_orb[p][warp] = sum;
        }
    }
    __syncthreads();

    if (tid < PPB) {
        int p = tid;
        float th0 = s_tp[p][0][0], ph0 = s_tp[p][0][1];
        float th1 = s_tp[p][1][0], ph1 = s_tp[p][1][1];
        float c0, s0, c1, s1;
        sincosf(0.5f*th0, &s0, &c0);
        sincosf(0.5f*th1, &s1, &c1);
        float hd = 0.5f*(ph0 - ph1);
        float chd, shd; sincosf(hd, &shd, &chd);
        float re = (c0*s1 - c1*s0) * chd;
        float im = (c0*s1 + c1*s0) * shd;
        float chord2 = re*re + im*im;
        float trunc = 1.f - expf(-100.f * chord2);
        float t2 = trunc * trunc;
        float a_r = s_orb[p][0], b_r = s_orb[p][1], c_r = s_orb[p][2], d_r = s_orb[p][3];
        float a_i = s_orb[p][4], b_i = s_orb[p][5], c_i = s_orb[p][6], d_i = s_orb[p][7];
        float det_r = (a_r*d_r - a_i*d_i) - (b_r*c_r - b_i*c_i);
        float det_i = (a_r*d_i + a_i*d_r) - (b_r*c_i + b_i*c_r);
        det_r *= t2; det_i *= t2;
        int i = s_ij[p][0], j = s_ij[p][1];
        g_A[i*NE + j] = make_float2(det_r, det_i);
        g_A[j*NE + i] = make_float2(-det_r, -det_i);
    }
}

// ---------------- cusp matrix + bosonic log sum ---------------------------
__global__ void cusp_bos_kernel(const float* __restrict__ electrons)
{
    int i = blockIdx.x, j = threadIdx.x;
    __shared__ double s_red[2][8];
    float thi = electrons[2*i], phi_ = electrons[2*i+1];
    float thj = electrons[2*j], phj  = electrons[2*j+1];
    float ci, si, cj, sj;
    sincosf(0.5f*thi, &si, &ci);
    sincosf(0.5f*thj, &sj, &cj);
    float hd = 0.5f*(phi_ - phj);
    float chd, shd; sincosf(hd, &shd, &chd);
    float er = (ci*sj - si*cj) * chd;
    float ei = (ci*sj + si*cj) * shd;

    float eye = (i == j) ? 1.f : 0.f;
    float cr = er + eye, cim = ei;
    float rc2 = cr*cr + cim*cim;
    float g = expf(-100.f * rc2);
    float2 a = (i == j) ? make_float2(0.f, 0.f) : g_A[i*NE + j];
    a.x += cr * g;
    a.y += cim * g;
    g_A[i*NE + j] = a;

    double lr = 0.0, li = 0.0;
    if (i != j) {
        float rho2 = er*er + ei*ei;
        lr = 0.5 * log((double)(0.01f + rho2));
        li = (double)atan2f(ei, er);
    }
    int lane = j & 31, wrp = j >> 5;
    #pragma unroll
    for (int off = 16; off; off >>= 1) {
        lr += __shfl_xor_sync(0xffffffffu, lr, off);
        li += __shfl_xor_sync(0xffffffffu, li, off);
    }
    if (lane == 0) { s_red[0][wrp] = lr; s_red[1][wrp] = li; }
    __syncthreads();
    if (j == 0) {
        double a0 = 0.0, a1 = 0.0;
        #pragma unroll
        for (int w = 0; w < 8; w++) { a0 += s_red[0][w]; a1 += s_red[1][w]; }
        atomicAdd(&g_acc[0], a0);
        atomicAdd(&g_acc[1], a1);
    }
}

// ---------------- complex LU with partial pivoting (slogdet) --------------
__device__ __forceinline__ float2 cmul(float2 a, float2 b) {
    return make_float2(a.x*b.x - a.y*b.y, a.x*b.y + a.y*b.x);
}

__global__ void __launch_bounds__(1024) lu_kernel()
{
    __shared__ float2 s_prow[256];
    __shared__ float2 s_l[256];
    __shared__ float  s_mx[8];
    __shared__ int    s_mi[8];
    __shared__ float2 s_inv;
    __shared__ int    s_piv;
    int tid = threadIdx.x;
    double logabs = 0.0, argsum = 0.0;
    int par = 0;

    for (int k = 0; k < 256; k++) {
        if (tid < 256) {
            float v = -1.f; int idx = tid;
            if (tid >= k) { float2 a = g_A[tid*256 + k]; v = fabsf(a.x) + fabsf(a.y); }
            #pragma unroll
            for (int off = 16; off; off >>= 1) {
                float ov = __shfl_xor_sync(0xffffffffu, v, off);
                int   oi = __shfl_xor_sync(0xffffffffu, idx, off);
                if (ov > v) { v = ov; idx = oi; }
            }
            if ((tid & 31) == 0) { s_mx[tid>>5] = v; s_mi[tid>>5] = idx; }
        }
        __syncthreads();
        if (tid == 0) {
            float bv = -1.f; int bi = k;
            #pragma unroll
            for (int w = 0; w < 8; w++) if (s_mx[w] > bv) { bv = s_mx[w]; bi = s_mi[w]; }
            s_piv = bi;
        }
        __syncthreads();
        int pv = s_piv;
        if (pv != k && tid < 256) {
            float2 t = g_A[k*256 + tid];
            g_A[k*256 + tid] = g_A[pv*256 + tid];
            g_A[pv*256 + tid] = t;
        }
        __syncthreads();
        if (tid == 0) {
            if (pv != k) par ^= 1;
            float2 u = g_A[k*256 + k];
            double n2 = (double)u.x*u.x + (double)u.y*u.y;
            logabs += 0.5 * log(n2);
            argsum += atan2((double)u.y, (double)u.x);
            float d = u.x*u.x + u.y*u.y;
            s_inv = make_float2(u.x/d, -u.y/d);
        }
        __syncthreads();
        if (tid < 256) {
            s_prow[tid] = g_A[k*256 + tid];
            if (tid > k) {
                float2 l = cmul(g_A[tid*256 + k], s_inv);
                s_l[tid] = l;
                g_A[tid*256 + k] = l;
            }
        }
        __syncthreads();
        {
            int c = tid & 255, r0 = tid >> 8;
            if (c > k) {
                float2 pr = s_prow[c];
                #pragma unroll 4
                for (int i = k + 1 + r0; i < 256; i += 4) {
                    float2 l = s_l[i];
                    float2 a = g_A[i*256 + c];
                    a.x -= l.x*pr.x - l.y*pr.y;
                    a.y -= l.x*pr.y + l.y*pr.x;
                    g_A[i*256 + c] = a;
                }
            }
        }
        __syncthreads();
    }
    if (tid == 0) { g_lu_logabs = logabs; g_lu_arg = argsum; g_lu_par = par; }
}

// ---------------- init + finalize -----------------------------------------
__global__ void init_kernel() { g_acc[0] = 0.0; g_acc[1] = 0.0; }

__global__ void finalize_kernel(float* out)
{
    const double PI = 3.14159265358979323846;
    double logabs = g_lu_logabs;
    double arg = g_lu_arg + (g_lu_par ? PI : 0.0);
    double w = fmod(arg, 2.0*PI);
    if (w >  PI) w -= 2.0*PI;
    if (w <= -PI) w += 2.0*PI;
    out[0] = (float)(0.5*logabs + g_acc[0]);
    out[1] = (float)(0.5*w      + g_acc[1]);
}

// ---------------- launch ---------------------------------------------------
extern "C" void kernel_launch(void* const* d_in, const int* in_sizes, int n_in,
                              void* d_out, int out_size)
{
    const float* electrons = (const float*)d_in[0];
    const float* W_in   = (const float*)d_in[1];
    const float* Wq     = (const float*)d_in[2];
    const float* bq     = (const float*)d_in[3];
    const float* Wk     = (const float*)d_in[4];
    const float* bk     = (const float*)d_in[5];
    const float* Wv     = (const float*)d_in[6];
    const float* bv     = (const float*)d_in[7];
    const float* Wo     = (const float*)d_in[8];
    const float* bo     = (const float*)d_in[9];
    const float* W1     = (const float*)d_in[10];
    const float* ln1_s  = (const float*)d_in[11];
    const float* ln1_b  = (const float*)d_in[12];
    const float* W2     = (const float*)d_in[13];
    const float* b2     = (const float*)d_in[14];
    const float* ln2_s  = (const float*)d_in[15];
    const float* ln2_b  = (const float*)d_in[16];
    const float* Worb_r = (const float*)d_in[17];
    const float* Worb_i = (const float*)d_in[18];

    cudaFuncSetAttribute(pair_kernel, cudaFuncAttributeMaxDynamicSharedMemorySize, SMEM_BYTES);

    convert_weights<<<12*65536/256, 256>>>(Wq, Wk, Wv, Wo, W1, W2);
    init_kernel<<<1, 1>>>();
    pair_kernel<<<NBLOCKS, 256, SMEM_BYTES>>>(electrons, W_in, bq, bk, bv, bo,
                                              ln1_s, ln1_b, b2, ln2_s, ln2_b,
                                              Worb_r, Worb_i);
    cusp_bos_kernel<<<NE, NE>>>(electrons);
    lu_kernel<<<1, 1024>>>();
    finalize_kernel<<<1, 1>>>((float*)d_out);
}